// round 15
// baseline (speedup 1.0000x reference)
#include <cuda_runtime.h>

#define F_IN   64
#define F_OUT  64
#define MAXN   50000

// Scratch: aggregated neighbor features, [node][16] float4 = [node][64] float
__device__ float4 g_agg[MAXN * (F_IN / 4)];

// ---------------------------------------------------------------------------
// Kernel 0: zero the aggregation buffer
// ---------------------------------------------------------------------------
__global__ void zero_agg_kernel(int n4) {
    int t = blockIdx.x * blockDim.x + threadIdx.x;
    if (t < n4) g_agg[t] = make_float4(0.f, 0.f, 0.f, 0.f);
}

// ---------------------------------------------------------------------------
// Kernel 1: edge scatter-add.  16 threads per edge, one float4 chunk each.
// x rows are 256B and L2-resident; red.global.add.v4.f32 does a fire-and-
// forget 16B reduction at the LTS slice (no return trip).
// ---------------------------------------------------------------------------
__global__ void scatter_kernel(const float4* __restrict__ x,
                               const int*    __restrict__ src,
                               const int*    __restrict__ dst,
                               int n_edges) {
    int t = blockIdx.x * blockDim.x + threadIdx.x;
    int e = t >> 4;
    if (e >= n_edges) return;
    int c = t & 15;
    int s = __ldg(&src[e]);
    int d = __ldg(&dst[e]);
    float4 v = x[(size_t)s * 16 + c];
    float4* p = &g_agg[(size_t)d * 16 + c];
    asm volatile("red.global.add.v4.f32 [%0], {%1,%2,%3,%4};"
                 :: "l"(p), "f"(v.x), "f"(v.y), "f"(v.z), "f"(v.w)
                 : "memory");
}

// ---------------------------------------------------------------------------
// Kernel 2: fused dual-GEMM epilogue.
//   out[n][o] = relu( sum_k agg[n][k]*W_rel[o][k]
//                   + sum_k   x[n][k]*W_root[o][k] + b[o] )
// Treated as one 50000 x 128 @ 128 x 64 GEMM with A = [agg | x],
// Wt = [W_rel^T ; W_root^T] (k-major in smem).
// Block: 128 threads = 8(tx:outs) x 16(ty:nodes). Tile: 128 nodes x 64 outs.
// Micro-tile: 8 nodes x 8 outs per thread (64 accs), 4 LDS.128 per k.
// ---------------------------------------------------------------------------
__global__ __launch_bounds__(128)
void fused_linear_kernel(const float4* __restrict__ x,       // [N][16]
                         const float4* __restrict__ W_rel4,  // [64][16]
                         const float*  __restrict__ b_rel,   // [64]
                         const float4* __restrict__ W_root4, // [64][16]
                         float*        __restrict__ out,     // [N][64]
                         int N) {
    extern __shared__ float sm[];
    float* As = sm;               // [128 k'][128 n]  (k' 0-63: agg, 64-127: x)
    float* Ws = sm + 128 * 128;   // [128 k'][64 o]

    const int tid = threadIdx.x;
    const int node_base = blockIdx.x * 128;

    // --- load A tile: thread owns node_local = tid, loops 32 float4 chunks.
    // STS addresses: As[k][tid] -> bank = tid % 32 across warp: conflict-free.
    {
        int node = node_base + tid;
        bool ok = node < N;
        #pragma unroll
        for (int c = 0; c < 32; c++) {
            float4 v = make_float4(0.f, 0.f, 0.f, 0.f);
            if (ok)
                v = (c < 16) ? g_agg[(size_t)node * 16 + c]
                             : x[(size_t)node * 16 + (c - 16)];
            int k = c * 4;
            As[(k + 0) * 128 + tid] = v.x;
            As[(k + 1) * 128 + tid] = v.y;
            As[(k + 2) * 128 + tid] = v.z;
            As[(k + 3) * 128 + tid] = v.w;
        }
    }

    // --- load W tile (transpose to k-major). 2048 float4 total.
    // STS addresses Ws[k][o] -> bank = o % 32 across warp: conflict-free.
    #pragma unroll
    for (int it = 0; it < 16; it++) {
        int idx = it * 128 + tid;
        int o = idx & 63;
        int q = idx >> 6;                       // 0..31 (float4 chunk of k')
        float4 v = (q < 16) ? W_rel4[o * 16 + q]
                            : W_root4[o * 16 + (q - 16)];
        int k = q * 4;                          // global k' (q>=16 maps past 64)
        Ws[(k + 0) * 64 + o] = v.x;
        Ws[(k + 1) * 64 + o] = v.y;
        Ws[(k + 2) * 64 + o] = v.z;
        Ws[(k + 3) * 64 + o] = v.w;
    }
    __syncthreads();

    const int tx = tid & 7;    // output group: o = tx*8 .. tx*8+7
    const int ty = tid >> 3;   // node group:   n = ty*8 .. ty*8+7

    float acc[8][8];
    #pragma unroll
    for (int i = 0; i < 8; i++)
        #pragma unroll
        for (int j = 0; j < 8; j++) acc[i][j] = 0.f;

    #pragma unroll 2
    for (int k = 0; k < 128; k++) {
        float4 a0 = *(const float4*)&As[k * 128 + ty * 8];
        float4 a1 = *(const float4*)&As[k * 128 + ty * 8 + 4];
        float4 w0 = *(const float4*)&Ws[k * 64 + tx * 8];
        float4 w1 = *(const float4*)&Ws[k * 64 + tx * 8 + 4];
        float a[8] = {a0.x, a0.y, a0.z, a0.w, a1.x, a1.y, a1.z, a1.w};
        float w[8] = {w0.x, w0.y, w0.z, w0.w, w1.x, w1.y, w1.z, w1.w};
        #pragma unroll
        for (int i = 0; i < 8; i++)
            #pragma unroll
            for (int j = 0; j < 8; j++)
                acc[i][j] = fmaf(a[i], w[j], acc[i][j]);
    }

    // --- epilogue: bias + relu + store
    float bias[8];
    #pragma unroll
    for (int j = 0; j < 8; j++) bias[j] = __ldg(&b_rel[tx * 8 + j]);

    #pragma unroll
    for (int i = 0; i < 8; i++) {
        int node = node_base + ty * 8 + i;
        if (node < N) {
            float r[8];
            #pragma unroll
            for (int j = 0; j < 8; j++)
                r[j] = fmaxf(acc[i][j] + bias[j], 0.f);
            float4* dst = (float4*)&out[(size_t)node * 64 + tx * 8];
            dst[0] = make_float4(r[0], r[1], r[2], r[3]);
            dst[1] = make_float4(r[4], r[5], r[6], r[7]);
        }
    }
}

// ---------------------------------------------------------------------------
extern "C" void kernel_launch(void* const* d_in, const int* in_sizes, int n_in,
                              void* d_out, int out_size) {
    const float* x      = (const float*)d_in[0];   // [50000][64]
    const float* W_rel  = (const float*)d_in[1];   // [64][64]
    const float* b_rel  = (const float*)d_in[2];   // [64]
    const float* W_root = (const float*)d_in[3];   // [64][64]
    const int*   ei     = (const int*)  d_in[4];   // [2][E]

    const int N = in_sizes[0] / F_IN;
    const int E = in_sizes[4] / 2;
    float* out = (float*)d_out;

    // 0) zero agg buffer
    {
        int n4 = N * (F_IN / 4);
        int blocks = (n4 + 255) / 256;
        zero_agg_kernel<<<blocks, 256>>>(n4);
    }

    // 1) scatter-add over edges (16 threads / edge)
    {
        long long total = (long long)E * 16;
        int blocks = (int)((total + 255) / 256);
        scatter_kernel<<<blocks, 256>>>((const float4*)x, ei, ei + E, E);
    }

    // 2) fused dual-GEMM + bias + relu
    {
        const int smem = (128 * 128 + 128 * 64) * (int)sizeof(float);  // 96 KB
        cudaFuncSetAttribute(fused_linear_kernel,
                             cudaFuncAttributeMaxDynamicSharedMemorySize, smem);
        int blocks = (N + 127) / 128;
        fused_linear_kernel<<<blocks, 128, smem>>>(
            (const float4*)x, (const float4*)W_rel, b_rel,
            (const float4*)W_root, out, N);
    }
}

// round 16
// speedup vs baseline: 1.0144x; 1.0144x over previous
#include <cuda_runtime.h>

#define F_IN   64
#define F_OUT  64
#define MAXN   50000

// Scratch: aggregated neighbor features, [node][16] float4 = [node][64] float
__device__ float4 g_agg[MAXN * (F_IN / 4)];

// ---------------------------------------------------------------------------
// Kernel 0: zero the aggregation buffer
// ---------------------------------------------------------------------------
__global__ void zero_agg_kernel(int n4) {
    int t = blockIdx.x * blockDim.x + threadIdx.x;
    if (t < n4) g_agg[t] = make_float4(0.f, 0.f, 0.f, 0.f);
}

// ---------------------------------------------------------------------------
// Kernel 1: edge scatter-add.  16 threads per edge, one float4 chunk each.
// x rows are 256B and L2-resident; red.global.add.v4.f32 does a fire-and-
// forget 16B reduction at the LTS slice (no return trip).
// ---------------------------------------------------------------------------
__global__ void scatter_kernel(const float4* __restrict__ x,
                               const int*    __restrict__ src,
                               const int*    __restrict__ dst,
                               int n_edges) {
    int t = blockIdx.x * blockDim.x + threadIdx.x;
    int e = t >> 4;
    if (e >= n_edges) return;
    int c = t & 15;
    int s = __ldg(&src[e]);
    int d = __ldg(&dst[e]);
    float4 v = x[(size_t)s * 16 + c];
    float4* p = &g_agg[(size_t)d * 16 + c];
    asm volatile("red.global.add.v4.f32 [%0], {%1,%2,%3,%4};"
                 :: "l"(p), "f"(v.x), "f"(v.y), "f"(v.z), "f"(v.w)
                 : "memory");
}

// ---------------------------------------------------------------------------
// Kernel 2: fused dual-GEMM epilogue.
//   out[n][o] = relu( sum_k agg[n][k]*W_rel[o][k]
//                   + sum_k   x[n][k]*W_root[o][k] + b[o] )
// Treated as one 50000 x 128 @ 128 x 64 GEMM with A = [agg | x],
// Wt = [W_rel^T ; W_root^T] (k-major in smem).
// Block: 128 threads = 8(tx:outs) x 16(ty:nodes). Tile: 128 nodes x 64 outs.
// Micro-tile: 8 nodes x 8 outs per thread (64 accs), 4 LDS.128 per k.
// ---------------------------------------------------------------------------
__global__ __launch_bounds__(128)
void fused_linear_kernel(const float4* __restrict__ x,       // [N][16]
                         const float4* __restrict__ W_rel4,  // [64][16]
                         const float*  __restrict__ b_rel,   // [64]
                         const float4* __restrict__ W_root4, // [64][16]
                         float*        __restrict__ out,     // [N][64]
                         int N) {
    extern __shared__ float sm[];
    float* As = sm;               // [128 k'][128 n]  (k' 0-63: agg, 64-127: x)
    float* Ws = sm + 128 * 128;   // [128 k'][64 o]

    const int tid = threadIdx.x;
    const int node_base = blockIdx.x * 128;

    // --- load A tile: thread owns node_local = tid, loops 32 float4 chunks.
    // STS addresses: As[k][tid] -> bank = tid % 32 across warp: conflict-free.
    {
        int node = node_base + tid;
        bool ok = node < N;
        #pragma unroll
        for (int c = 0; c < 32; c++) {
            float4 v = make_float4(0.f, 0.f, 0.f, 0.f);
            if (ok)
                v = (c < 16) ? g_agg[(size_t)node * 16 + c]
                             : x[(size_t)node * 16 + (c - 16)];
            int k = c * 4;
            As[(k + 0) * 128 + tid] = v.x;
            As[(k + 1) * 128 + tid] = v.y;
            As[(k + 2) * 128 + tid] = v.z;
            As[(k + 3) * 128 + tid] = v.w;
        }
    }

    // --- load W tile (transpose to k-major). 2048 float4 total.
    // STS addresses Ws[k][o] -> bank = o % 32 across warp: conflict-free.
    #pragma unroll
    for (int it = 0; it < 16; it++) {
        int idx = it * 128 + tid;
        int o = idx & 63;
        int q = idx >> 6;                       // 0..31 (float4 chunk of k')
        float4 v = (q < 16) ? W_rel4[o * 16 + q]
                            : W_root4[o * 16 + (q - 16)];
        int k = q * 4;                          // global k' (q>=16 maps past 64)
        Ws[(k + 0) * 64 + o] = v.x;
        Ws[(k + 1) * 64 + o] = v.y;
        Ws[(k + 2) * 64 + o] = v.z;
        Ws[(k + 3) * 64 + o] = v.w;
    }
    __syncthreads();

    const int tx = tid & 7;    // output group: o = tx*8 .. tx*8+7
    const int ty = tid >> 3;   // node group:   n = ty*8 .. ty*8+7

    float acc[8][8];
    #pragma unroll
    for (int i = 0; i < 8; i++)
        #pragma unroll
        for (int j = 0; j < 8; j++) acc[i][j] = 0.f;

    #pragma unroll 2
    for (int k = 0; k < 128; k++) {
        float4 a0 = *(const float4*)&As[k * 128 + ty * 8];
        float4 a1 = *(const float4*)&As[k * 128 + ty * 8 + 4];
        float4 w0 = *(const float4*)&Ws[k * 64 + tx * 8];
        float4 w1 = *(const float4*)&Ws[k * 64 + tx * 8 + 4];
        float a[8] = {a0.x, a0.y, a0.z, a0.w, a1.x, a1.y, a1.z, a1.w};
        float w[8] = {w0.x, w0.y, w0.z, w0.w, w1.x, w1.y, w1.z, w1.w};
        #pragma unroll
        for (int i = 0; i < 8; i++)
            #pragma unroll
            for (int j = 0; j < 8; j++)
                acc[i][j] = fmaf(a[i], w[j], acc[i][j]);
    }

    // --- epilogue: bias + relu + store
    float bias[8];
    #pragma unroll
    for (int j = 0; j < 8; j++) bias[j] = __ldg(&b_rel[tx * 8 + j]);

    #pragma unroll
    for (int i = 0; i < 8; i++) {
        int node = node_base + ty * 8 + i;
        if (node < N) {
            float r[8];
            #pragma unroll
            for (int j = 0; j < 8; j++)
                r[j] = fmaxf(acc[i][j] + bias[j], 0.f);
            float4* dst = (float4*)&out[(size_t)node * 64 + tx * 8];
            dst[0] = make_float4(r[0], r[1], r[2], r[3]);
            dst[1] = make_float4(r[4], r[5], r[6], r[7]);
        }
    }
}

// ---------------------------------------------------------------------------
extern "C" void kernel_launch(void* const* d_in, const int* in_sizes, int n_in,
                              void* d_out, int out_size) {
    const float* x      = (const float*)d_in[0];   // [50000][64]
    const float* W_rel  = (const float*)d_in[1];   // [64][64]
    const float* b_rel  = (const float*)d_in[2];   // [64]
    const float* W_root = (const float*)d_in[3];   // [64][64]
    const int*   ei     = (const int*)  d_in[4];   // [2][E]

    const int N = in_sizes[0] / F_IN;
    const int E = in_sizes[4] / 2;
    float* out = (float*)d_out;

    // 0) zero agg buffer
    {
        int n4 = N * (F_IN / 4);
        int blocks = (n4 + 255) / 256;
        zero_agg_kernel<<<blocks, 256>>>(n4);
    }

    // 1) scatter-add over edges (16 threads / edge)
    {
        long long total = (long long)E * 16;
        int blocks = (int)((total + 255) / 256);
        scatter_kernel<<<blocks, 256>>>((const float4*)x, ei, ei + E, E);
    }

    // 2) fused dual-GEMM + bias + relu
    {
        const int smem = (128 * 128 + 128 * 64) * (int)sizeof(float);  // 96 KB
        cudaFuncSetAttribute(fused_linear_kernel,
                             cudaFuncAttributeMaxDynamicSharedMemorySize, smem);
        int blocks = (N + 127) / 128;
        fused_linear_kernel<<<blocks, 128, smem>>>(
            (const float4*)x, (const float4*)W_rel, b_rel,
            (const float4*)W_root, out, N);
    }
}